// round 7
// baseline (speedup 1.0000x reference)
#include <cuda_runtime.h>
#include <math.h>

#define Bsz 8
#define Esz 2000
#define Nsz 10000
#define NRELc 25
#define Ksz 16
#define Tsz 3
#define Lsz 32
#define TAU1f 10.0f
#define BL 256               // B*L columns
#define COL2 128             // BL/2 float2 columns
#define TPB 2                // tails per block

// ---------------- scratch (static device globals) ----------------
__device__ int      g_heads[Nsz];
__device__ int      g_tails[Nsz];
__device__ int      g_rels[Nsz];
__device__ unsigned g_trips[Nsz];        // head(11b) | rel<<11, CSR by tail
__device__ int      g_rowptr[Esz + 1];
__device__ unsigned g_mask[Esz];
__device__ int      g_tidx[Esz];
__device__ int      g_ent[Bsz];
__device__ float    g_val[Bsz];
__device__ float    g_hx0[BL];
__device__ float    g_wp[Tsz * NRELc * Lsz];        // [t][r][l]
__device__ float    g_shp[Tsz * (NRELc - 1) * Lsz]; // [t][j][l]
__device__ float    g_shtp[Tsz * Ksz * Lsz];        // [t][k][l]
__device__ float    g_ab[Tsz * Lsz * 2];
__device__ float    g_tw[Lsz];
__device__ float    g_sA[Esz * BL];
__device__ float    g_sB[Esz * BL];
__device__ unsigned g_done;              // last-block-done counter (self-resetting)

__device__ __forceinline__ float clip01(float x) { return fminf(fmaxf(x, 0.0f), 1.0f); }

// ============ 1) streaming extraction + fused mid (last block) ============
__global__ void __launch_bounds__(1024, 1)
k_setup(const float4* __restrict__ e2t,
        const float4* __restrict__ t2e,
        const float4* __restrict__ t2r,
        const float*  __restrict__ input_x,
        const float*  __restrict__ type_mat,
        const float* __restrict__ alpha, const float* __restrict__ beta,
        const float* __restrict__ alpha_x, const float* __restrict__ beta_x,
        const float* __restrict__ h_x, const float* __restrict__ h_x_type,
        const float* __restrict__ w, const float* __restrict__ h,
        const float* __restrict__ h_type, const float* __restrict__ weight) {
    unsigned tid = blockIdx.x * blockDim.x + threadIdx.x;
    unsigned stride = gridDim.x * blockDim.x;

    for (unsigned i = tid; i < Bsz * Esz; i += stride) {
        float v = input_x[i];
        if (v != 0.0f) { g_ent[i / Esz] = (int)(i % Esz); g_val[i / Esz] = v; }
    }
    for (unsigned i = tid; i < Esz * Ksz; i += stride)
        if (type_mat[i] != 0.0f) g_tidx[i / Ksz] = (int)(i % Ksz);

    const unsigned n3 = Nsz * NRELc / 4;
    for (unsigned i = tid; i < n3; i += stride) {
        float4 v = t2r[i];
        unsigned base = i * 4u;
        if (v.x != 0.0f) { unsigned id = base + 0; g_rels[id / NRELc] = (int)(id % NRELc); }
        if (v.y != 0.0f) { unsigned id = base + 1; g_rels[id / NRELc] = (int)(id % NRELc); }
        if (v.z != 0.0f) { unsigned id = base + 2; g_rels[id / NRELc] = (int)(id % NRELc); }
        if (v.w != 0.0f) { unsigned id = base + 3; g_rels[id / NRELc] = (int)(id % NRELc); }
    }
    const unsigned n1 = (unsigned)Esz * Nsz / 4;   // e2triple [E,N] -> heads
    for (unsigned i = tid; i < n1; i += stride) {
        float4 v = e2t[i];
        unsigned base = i * 4u;
        if (v.x != 0.0f) { unsigned id = base + 0; g_heads[id % Nsz] = (int)(id / Nsz); }
        if (v.y != 0.0f) { unsigned id = base + 1; g_heads[id % Nsz] = (int)(id / Nsz); }
        if (v.z != 0.0f) { unsigned id = base + 2; g_heads[id % Nsz] = (int)(id / Nsz); }
        if (v.w != 0.0f) { unsigned id = base + 3; g_heads[id % Nsz] = (int)(id / Nsz); }
    }
    const unsigned n2 = (unsigned)Nsz * Esz / 4;   // triple2e [N,E] -> tails
    for (unsigned i = tid; i < n2; i += stride) {
        float4 v = t2e[i];
        unsigned base = i * 4u;
        if (v.x != 0.0f) { unsigned id = base + 0; g_tails[id / Esz] = (int)(id % Esz); }
        if (v.y != 0.0f) { unsigned id = base + 1; g_tails[id / Esz] = (int)(id % Esz); }
        if (v.z != 0.0f) { unsigned id = base + 2; g_tails[id / Esz] = (int)(id % Esz); }
        if (v.w != 0.0f) { unsigned id = base + 3; g_tails[id / Esz] = (int)(id % Esz); }
    }

    // ---- last-block-done: the final block performs the mid phase ----
    __shared__ bool s_last;
    __threadfence();
    if (threadIdx.x == 0) {
        unsigned prev = atomicAdd(&g_done, 1u);
        s_last = (prev == gridDim.x - 1);
        if (s_last) g_done = 0u;   // reset for next graph replay
    }
    __syncthreads();
    if (!s_last) return;
    __threadfence();   // acquire: make other blocks' writes visible

    // ================= mid phase (single block, 1024 threads) =================
    __shared__ int      scnt[Esz];
    __shared__ unsigned smask[Esz];
    __shared__ int      sfill[Esz];
    __shared__ int      sscan[1024];
    __shared__ float    shx[Bsz * NRELc];
    __shared__ float    shxb[Bsz * (NRELc - 1)];
    __shared__ int      sent[Bsz];
    __shared__ float    sval[Bsz];

    int t = threadIdx.x;
    for (int i = t; i < Esz; i += 1024) { scnt[i] = 0; smask[i] = 0u; }
    if (t < Bsz * NRELc) shx[t] = 0.0f;
    if (t < Bsz) { sent[t] = g_ent[t]; sval[t] = g_val[t]; }
    __syncthreads();

    for (int n = t; n < Nsz; n += 1024) {
        int tl = g_tails[n], r = g_rels[n], hd = g_heads[n];
        atomicAdd(&scnt[tl], 1);
        if (r < NRELc - 1) atomicOr(&smask[tl], 1u << r);
#pragma unroll
        for (int b = 0; b < Bsz; b++)
            if (hd == sent[b]) atomicAdd(&shx[b * NRELc + r], sval[b]);
    }
    __syncthreads();

    for (int i = t; i < Esz; i += 1024) g_mask[i] = smask[i];

    // tables
    if (t < Tsz * Lsz) {
        int tt = t / Lsz, l = t % Lsz;
        const float* wr = w + (tt * Lsz + l) * NRELc;
        float m = -1e30f;
#pragma unroll
        for (int r = 0; r < NRELc; r++) m = fmaxf(m, wr[r]);
        float s = 0.0f, ev[NRELc];
#pragma unroll
        for (int r = 0; r < NRELc; r++) { ev[r] = expf(wr[r] - m); s += ev[r]; }
        float inv = 1.0f / s;
#pragma unroll
        for (int r = 0; r < NRELc; r++)
            g_wp[(tt * NRELc + r) * Lsz + l] = ev[r] * inv;
        g_ab[(tt * Lsz + l) * 2 + 0] = clip01(alpha[tt * Lsz + l] / TAU1f);
        g_ab[(tt * Lsz + l) * 2 + 1] = clip01(beta[tt * Lsz + l] / TAU1f);
    }
    for (int i = t; i < Tsz * (NRELc - 1) * Lsz; i += 1024) {
        int tt = i / ((NRELc - 1) * Lsz);
        int rem = i % ((NRELc - 1) * Lsz);
        int j = rem / Lsz, l = rem % Lsz;
        g_shp[i] = clip01(h[(tt * Lsz + l) * (NRELc - 1) + j] / TAU1f);
    }
    for (int i = t; i < Tsz * Ksz * Lsz; i += 1024) {
        int tt = i / (Ksz * Lsz);
        int rem = i % (Ksz * Lsz);
        int k = rem / Lsz, l = rem % Lsz;
        g_shtp[i] = clip01(h_type[(tt * Lsz + l) * Ksz + k] / TAU1f);
    }
    if (t < Lsz) g_tw[t] = tanhf(weight[t]);

    // exclusive scan
    int c0 = (2 * t < Esz) ? scnt[2 * t] : 0;
    int c1 = (2 * t + 1 < Esz) ? scnt[2 * t + 1] : 0;
    sscan[t] = c0 + c1;
    __syncthreads();
    for (int off = 1; off < 1024; off <<= 1) {
        int v = (t >= off) ? sscan[t - off] : 0;
        __syncthreads();
        sscan[t] += v;
        __syncthreads();
    }
    int excl = (t > 0) ? sscan[t - 1] : 0;
    if (2 * t < Esz)     { g_rowptr[2 * t] = excl;          sfill[2 * t] = excl; }
    if (2 * t + 1 < Esz) { g_rowptr[2 * t + 1] = excl + c0; sfill[2 * t + 1] = excl + c0; }
    if (t == 0) g_rowptr[Esz] = Nsz;

    if (t < Bsz * (NRELc - 1)) {
        int b = t / (NRELc - 1), j = t % (NRELc - 1);
        int col = (j < 12) ? (12 + j) : (j - 12);
        shxb[t] = clip01(shx[b * NRELc + col]);
    }
    __syncthreads();

    if (t < BL) {
        int b = t / Lsz, l = t % Lsz;
        float a  = clip01(alpha[l] / TAU1f);
        float bb = clip01(beta[l] / TAU1f);
        float gate = 1.0f - clip01(clip01(alpha_x[l] / TAU1f) + clip01(beta_x[l] / TAU1f));
        float htx = 0.0f;
#pragma unroll
        for (int k = 0; k < Ksz; k++)
            htx += type_mat[sent[b] * Ksz + k] * clip01(h_x_type[l * Ksz + k] / TAU1f);
        htx *= sval[b];
        float hxl = 0.0f;
#pragma unroll
        for (int j = 0; j < NRELc - 1; j++)
            hxl += shxb[b * (NRELc - 1) + j] * clip01(h_x[l * (NRELc - 1) + j] / TAU1f);
        g_hx0[t] = clip01(a * htx + bb * hxl) + gate;
    }
    __syncthreads();

    for (int n = t; n < Nsz; n += 1024) {
        int tl = g_tails[n];
        int pos = atomicAdd(&sfill[tl], 1);
        g_trips[pos] = (unsigned)g_heads[n] | ((unsigned)g_rels[n] << 11);
    }
}

// ============ 2) propagation: thread = 2 columns (float2), 2 tails/block ============
template <int T>
__global__ void __launch_bounds__(TPB * COL2)
k_prop(float* __restrict__ out) {
    const int tid = threadIdx.x;
    const int g = tid >> 7;          // local tail 0..1
    const int c = tid & 127;         // float2 column slot
    const int b = c >> 4;            // batch row (16 float2 slots per b)
    const int e0 = blockIdx.x * TPB;
    const int e  = e0 + g;

    __shared__ float shid[TPB][Lsz];

    if (tid < TPB * Lsz) {
        int gg = tid >> 5, l = tid & 31;
        int ee = e0 + gg;
        float a  = g_ab[(T * Lsz + l) * 2 + 0];
        float bb = g_ab[(T * Lsz + l) * 2 + 1];
        float s1 = g_shtp[(T * Ksz + g_tidx[ee]) * Lsz + l];
        float s2 = 0.0f;
        unsigned m = g_mask[ee];
        while (m) { int jj = __ffs(m) - 1; s2 += g_shp[(T * (NRELc - 1) + jj) * Lsz + l]; m &= m - 1; }
        shid[gg][l] = clip01(a * s1 + bb * s2) + (1.0f - clip01(a + bb));
    }
    __syncthreads();

    const float2* prevbuf = (const float2*)((T == 1) ? g_sA : g_sB);
    float2* dstbuf = (float2*)((T == 0) ? g_sA : g_sB);
    const float2* wp2 = (const float2*)g_wp;

    int sentb = 0; float svalb = 0.0f;
    if (T == 0) { sentb = g_ent[b]; svalb = g_val[b]; }

    const int beg = g_rowptr[e];
    const int end = g_rowptr[e + 1];

    float2 acc = make_float2(0.f, 0.f);
    int j = beg;
    // unrolled-by-2 body: 4 independent loads per iteration
    for (; j + 2 <= end; j += 2) {
        unsigned u0 = __ldg(&g_trips[j]);
        unsigned u1 = __ldg(&g_trips[j + 1]);
        unsigned h0 = u0 & 0x7ffu, r0 = u0 >> 11;
        unsigned h1 = u1 & 0x7ffu, r1 = u1 >> 11;
        float2 v0, v1;
        if (T == 0) {
            float s0 = ((int)h0 == sentb) ? svalb : 0.0f;
            float s1 = ((int)h1 == sentb) ? svalb : 0.0f;
            v0 = make_float2(s0, s0); v1 = make_float2(s1, s1);
        } else {
            v0 = prevbuf[h0 * COL2 + c];
            v1 = prevbuf[h1 * COL2 + c];
        }
        float2 w0 = wp2[(T * NRELc + r0) * 16 + (c & 15)];
        float2 w1 = wp2[(T * NRELc + r1) * 16 + (c & 15)];
        acc.x = fmaf(v0.x, w0.x, acc.x); acc.y = fmaf(v0.y, w0.y, acc.y);
        acc.x = fmaf(v1.x, w1.x, acc.x); acc.y = fmaf(v1.y, w1.y, acc.y);
    }
    if (j < end) {
        unsigned u = __ldg(&g_trips[j]);
        unsigned hh = u & 0x7ffu, rr = u >> 11;
        float2 v;
        if (T == 0) { float s = ((int)hh == sentb) ? svalb : 0.0f; v = make_float2(s, s); }
        else        { v = prevbuf[hh * COL2 + c]; }
        float2 wv = wp2[(T * NRELc + rr) * 16 + (c & 15)];
        acc.x = fmaf(v.x, wv.x, acc.x); acc.y = fmaf(v.y, wv.y, acc.y);
    }

    float2 hid = ((const float2*)shid[g])[c & 15];
    float2 val = make_float2(acc.x * hid.x, acc.y * hid.y);
    if (T == 0) {
        float2 sc = ((const float2*)g_hx0)[c];
        val.x *= sc.x; val.y *= sc.y;
    }

    if (T == 2) {
        float2 tw = ((const float2*)g_tw)[c & 15];
        float r = val.x * tw.x + val.y * tw.y;
#pragma unroll
        for (int off = 8; off > 0; off >>= 1)
            r += __shfl_xor_sync(0xffffffffu, r, off);
        if ((c & 15) == 0) out[b * Esz + e] = r;
    } else {
        dstbuf[e * COL2 + c] = val;
    }
}

// ---------------- launch ----------------
extern "C" void kernel_launch(void* const* d_in, const int* in_sizes, int n_in,
                              void* d_out, int out_size) {
    const float* input_x  = (const float*)d_in[0];
    const float* type_mat = (const float*)d_in[1];
    const float* e2triple = (const float*)d_in[2];
    const float* triple2e = (const float*)d_in[3];
    const float* triple2r = (const float*)d_in[4];
    const float* w        = (const float*)d_in[5];
    const float* weight   = (const float*)d_in[6];
    const float* h        = (const float*)d_in[7];
    const float* h_x      = (const float*)d_in[8];
    const float* h_type   = (const float*)d_in[9];
    const float* h_x_type = (const float*)d_in[10];
    const float* alpha    = (const float*)d_in[11];
    const float* beta     = (const float*)d_in[12];
    const float* alpha_x  = (const float*)d_in[13];
    const float* beta_x   = (const float*)d_in[14];
    float* out = (float*)d_out;

    k_setup<<<296, 1024>>>((const float4*)e2triple, (const float4*)triple2e,
                           (const float4*)triple2r, input_x, type_mat,
                           alpha, beta, alpha_x, beta_x, h_x, h_x_type,
                           w, h, h_type, weight);
    k_prop<0><<<Esz / TPB, TPB * COL2>>>(out);
    k_prop<1><<<Esz / TPB, TPB * COL2>>>(out);
    k_prop<2><<<Esz / TPB, TPB * COL2>>>(out);
}